// round 5
// baseline (speedup 1.0000x reference)
#include <cuda_runtime.h>
#include <math.h>

#define C 128
#define CV 32          // C/4 float4 per row
#define HID 8
#define NB 16

// Scratch (no allocations allowed)
__device__ float g_sums[NB][C];
__device__ float g_counts[NB];
__device__ float g_gate[NB][C];

// ---------------------------------------------------------------------------
// 0) zero accumulators (must run every launch for determinism)
// ---------------------------------------------------------------------------
__global__ void zero_kernel() {
    int t = threadIdx.x;
    for (int i = t; i < NB * C; i += blockDim.x) ((float*)g_sums)[i] = 0.0f;
    if (t < NB) g_counts[t] = 0.0f;
}

// ---------------------------------------------------------------------------
// 1) segment sum, branchless inner loop.
//    Block owns contiguous rows [row0,row1). Since bidx is sorted with only
//    16 segments, the block intersects very few segments; find the interior
//    boundaries by binary search (cached, negligible), then stream each
//    segment with a pure load/FADD loop — no per-row branch, no per-row
//    bidx load. One warp owns one row per step: lane l -> float4 slot l.
// ---------------------------------------------------------------------------
__device__ __forceinline__ int lower_bound_idx(const int* __restrict__ bidx,
                                               int lo, int hi, int val) {
    // first index in [lo,hi) with bidx[idx] >= val
    while (lo < hi) {
        int mid = (lo + hi) >> 1;
        if (bidx[mid] < val) lo = mid + 1; else hi = mid;
    }
    return lo;
}

__global__ __launch_bounds__(256) void reduce_kernel(
    const float4* __restrict__ x, const int* __restrict__ bidx,
    int n, int rows_per_block)
{
    int row0 = blockIdx.x * rows_per_block;
    int row1 = row0 + rows_per_block;
    if (row1 > n) row1 = n;
    if (row0 >= row1) return;

    int warp = threadIdx.x >> 5;
    int lane = threadIdx.x & 31;

    int b_first = bidx[row0];
    int b_last  = bidx[row1 - 1];

    int seg_start = row0;
    for (int b = b_first; b <= b_last; b++) {
        int seg_end = (b == b_last) ? row1
                    : lower_bound_idx(bidx, seg_start, row1, b + 1);

        // --- branchless accumulate over [seg_start, seg_end) ---
        float4 acc = make_float4(0.f, 0.f, 0.f, 0.f);
        int r = seg_start + warp;
        for (; r + 24 < seg_end; r += 32) {
            float4 v0 = x[(size_t)(r)      * CV + lane];
            float4 v1 = x[(size_t)(r + 8)  * CV + lane];
            float4 v2 = x[(size_t)(r + 16) * CV + lane];
            float4 v3 = x[(size_t)(r + 24) * CV + lane];
            acc.x += v0.x; acc.y += v0.y; acc.z += v0.z; acc.w += v0.w;
            acc.x += v1.x; acc.y += v1.y; acc.z += v1.z; acc.w += v1.w;
            acc.x += v2.x; acc.y += v2.y; acc.z += v2.z; acc.w += v2.w;
            acc.x += v3.x; acc.y += v3.y; acc.z += v3.z; acc.w += v3.w;
        }
        for (; r < seg_end; r += 8) {
            float4 v = x[(size_t)r * CV + lane];
            acc.x += v.x; acc.y += v.y; acc.z += v.z; acc.w += v.w;
        }

        // flush (rare: once per segment per warp)
        int seg_len = seg_end - seg_start;
        if (seg_len > 0) {
            float* dst = &g_sums[b][lane * 4];
            atomicAdd(dst + 0, acc.x);
            atomicAdd(dst + 1, acc.y);
            atomicAdd(dst + 2, acc.z);
            atomicAdd(dst + 3, acc.w);
            if (lane == 0 && warp == 0)
                atomicAdd(&g_counts[b], (float)seg_len);
        }
        seg_start = seg_end;
    }
}

// ---------------------------------------------------------------------------
// 2) tiny MLP: mean -> Linear(128,8) -> ReLU -> Linear(8,128) -> sigmoid
// ---------------------------------------------------------------------------
__global__ __launch_bounds__(128) void mlp_kernel(
    const float* __restrict__ W1, const float* __restrict__ b1,
    const float* __restrict__ W2, const float* __restrict__ b2)
{
    __shared__ float s_mean[NB][C];
    __shared__ float s_h[NB][HID];

    int t = threadIdx.x;  // 0..127

    for (int i = t; i < NB * C; i += 128) {
        int b = i / C, c = i % C;
        float cn = fmaxf(g_counts[b], 1.0f);
        s_mean[b][c] = g_sums[b][c] / cn;
    }
    __syncthreads();

    {
        int b = t / HID, j = t % HID;
        float acc = b1[j];
        #pragma unroll 8
        for (int c = 0; c < C; c++) acc += s_mean[b][c] * W1[c * HID + j];
        s_h[b][j] = fmaxf(acc, 0.0f);
    }
    __syncthreads();

    {
        int c = t;
        float w2c[HID];
        #pragma unroll
        for (int j = 0; j < HID; j++) w2c[j] = W2[j * C + c];
        float bias = b2[c];
        for (int b = 0; b < NB; b++) {
            float acc = bias;
            #pragma unroll
            for (int j = 0; j < HID; j++) acc += s_h[b][j] * w2c[j];
            g_gate[b][c] = 1.0f / (1.0f + expf(-acc));
        }
    }
}

// ---------------------------------------------------------------------------
// 3) apply gate: out[r][c] = x[r][c] * gate[bidx[r]][c]   (512 MB traffic)
//    x2 unroll with front-batched loads. (At LTS cap — leave alone.)
// ---------------------------------------------------------------------------
__global__ __launch_bounds__(256) void apply_kernel(
    const float4* __restrict__ x, const int* __restrict__ bidx,
    float4* __restrict__ out, int n)
{
    __shared__ float4 s_gate[NB][CV];  // 8 KB
    for (int i = threadIdx.x; i < NB * CV; i += blockDim.x)
        ((float4*)s_gate)[i] = ((const float4*)g_gate)[i];
    __syncthreads();

    int lane = threadIdx.x & 31;
    int gwarp = (blockIdx.x * blockDim.x + threadIdx.x) >> 5;
    int nwarps = (gridDim.x * blockDim.x) >> 5;

    int r = gwarp;
    for (; r + nwarps < n; r += 2 * nwarps) {
        int r2 = r + nwarps;
        int b0 = bidx[r];
        int b1 = bidx[r2];
        float4 v0 = x[(size_t)r  * CV + lane];
        float4 v1 = x[(size_t)r2 * CV + lane];
        float4 g0 = s_gate[b0][lane];
        float4 g1 = s_gate[b1][lane];
        v0.x *= g0.x; v0.y *= g0.y; v0.z *= g0.z; v0.w *= g0.w;
        v1.x *= g1.x; v1.y *= g1.y; v1.z *= g1.z; v1.w *= g1.w;
        out[(size_t)r  * CV + lane] = v0;
        out[(size_t)r2 * CV + lane] = v1;
    }
    if (r < n) {
        int b = bidx[r];
        float4 v = x[(size_t)r * CV + lane];
        float4 g = s_gate[b][lane];
        v.x *= g.x; v.y *= g.y; v.z *= g.z; v.w *= g.w;
        out[(size_t)r * CV + lane] = v;
    }
}

// ---------------------------------------------------------------------------
extern "C" void kernel_launch(void* const* d_in, const int* in_sizes, int n_in,
                              void* d_out, int out_size)
{
    const float* x    = (const float*)d_in[0];
    const int*   bidx = (const int*)d_in[1];
    const float* W1   = (const float*)d_in[2];
    const float* b1   = (const float*)d_in[3];
    const float* W2   = (const float*)d_in[4];
    const float* b2   = (const float*)d_in[5];
    float* out = (float*)d_out;

    int n = in_sizes[1];  // number of rows (batch_idx has N entries)

    zero_kernel<<<1, 256>>>();

    const int RED_BLOCKS = 592;  // 4 waves of 148 SMs
    int rows_per_block = (n + RED_BLOCKS - 1) / RED_BLOCKS;
    reduce_kernel<<<RED_BLOCKS, 256>>>((const float4*)x, bidx, n, rows_per_block);

    mlp_kernel<<<1, 128>>>(W1, b1, W2, b2);

    const int APPLY_BLOCKS = 1184;  // 8 waves
    apply_kernel<<<APPLY_BLOCKS, 256>>>((const float4*)x, bidx, (float4*)out, n);
}

// round 6
// speedup vs baseline: 1.0386x; 1.0386x over previous
#include <cuda_runtime.h>
#include <math.h>

#define C 128
#define CV 32          // C/4 float4 per row
#define HID 8
#define NB 16
#define RED_BLOCKS 592 // exactly 4 co-resident blocks x 148 SMs = one wave

// Scratch (no allocations allowed). __device__ globals are zero-initialized
// at module load; mlp_kernel re-zeroes them after consuming, so every call
// (correctness, capture, replay) starts from zeros.
__device__ float g_sums[NB][C];
__device__ float g_counts[NB];
__device__ float g_gate[NB][C];

// ---------------------------------------------------------------------------
// 1) segment sum. Block owns contiguous rows [row0,row1); bidx sorted, 16
//    segments -> block spans few segments; binary-search boundaries (cached),
//    then stream each segment with a pure load/FADD loop.
//    Unroll 8 (MLP_p1 = 8) + two accumulators to halve the FADD dep chain.
// ---------------------------------------------------------------------------
__device__ __forceinline__ int lower_bound_idx(const int* __restrict__ bidx,
                                               int lo, int hi, int val) {
    while (lo < hi) {
        int mid = (lo + hi) >> 1;
        if (bidx[mid] < val) lo = mid + 1; else hi = mid;
    }
    return lo;
}

__global__ __launch_bounds__(256) void reduce_kernel(
    const float4* __restrict__ x, const int* __restrict__ bidx,
    int n, int rows_per_block)
{
    int row0 = blockIdx.x * rows_per_block;
    int row1 = row0 + rows_per_block;
    if (row1 > n) row1 = n;
    if (row0 >= row1) return;

    int warp = threadIdx.x >> 5;
    int lane = threadIdx.x & 31;

    int b_first = bidx[row0];
    int b_last  = bidx[row1 - 1];

    int seg_start = row0;
    for (int b = b_first; b <= b_last; b++) {
        int seg_end = (b == b_last) ? row1
                    : lower_bound_idx(bidx, seg_start, row1, b + 1);

        float4 accA = make_float4(0.f, 0.f, 0.f, 0.f);
        float4 accB = make_float4(0.f, 0.f, 0.f, 0.f);

        int r = seg_start + warp;
        for (; r + 56 < seg_end; r += 64) {
            float4 v0 = x[(size_t)(r)      * CV + lane];
            float4 v1 = x[(size_t)(r + 8)  * CV + lane];
            float4 v2 = x[(size_t)(r + 16) * CV + lane];
            float4 v3 = x[(size_t)(r + 24) * CV + lane];
            float4 v4 = x[(size_t)(r + 32) * CV + lane];
            float4 v5 = x[(size_t)(r + 40) * CV + lane];
            float4 v6 = x[(size_t)(r + 48) * CV + lane];
            float4 v7 = x[(size_t)(r + 56) * CV + lane];
            accA.x += v0.x; accA.y += v0.y; accA.z += v0.z; accA.w += v0.w;
            accB.x += v1.x; accB.y += v1.y; accB.z += v1.z; accB.w += v1.w;
            accA.x += v2.x; accA.y += v2.y; accA.z += v2.z; accA.w += v2.w;
            accB.x += v3.x; accB.y += v3.y; accB.z += v3.z; accB.w += v3.w;
            accA.x += v4.x; accA.y += v4.y; accA.z += v4.z; accA.w += v4.w;
            accB.x += v5.x; accB.y += v5.y; accB.z += v5.z; accB.w += v5.w;
            accA.x += v6.x; accA.y += v6.y; accA.z += v6.z; accA.w += v6.w;
            accB.x += v7.x; accB.y += v7.y; accB.z += v7.z; accB.w += v7.w;
        }
        for (; r < seg_end; r += 8) {
            float4 v = x[(size_t)r * CV + lane];
            accA.x += v.x; accA.y += v.y; accA.z += v.z; accA.w += v.w;
        }

        int seg_len = seg_end - seg_start;
        if (seg_len > 0) {
            float* dst = &g_sums[b][lane * 4];
            atomicAdd(dst + 0, accA.x + accB.x);
            atomicAdd(dst + 1, accA.y + accB.y);
            atomicAdd(dst + 2, accA.z + accB.z);
            atomicAdd(dst + 3, accA.w + accB.w);
            if (lane == 0 && warp == 0)
                atomicAdd(&g_counts[b], (float)seg_len);
        }
        seg_start = seg_end;
    }
}

// ---------------------------------------------------------------------------
// 2) tiny MLP: mean -> Linear(128,8) -> ReLU -> Linear(8,128) -> sigmoid.
//    Also re-zeroes g_sums/g_counts for the next call (replaces zero_kernel).
// ---------------------------------------------------------------------------
__global__ __launch_bounds__(128) void mlp_kernel(
    const float* __restrict__ W1, const float* __restrict__ b1,
    const float* __restrict__ W2, const float* __restrict__ b2)
{
    __shared__ float s_mean[NB][C];
    __shared__ float s_h[NB][HID];

    int t = threadIdx.x;  // 0..127

    for (int i = t; i < NB * C; i += 128) {
        int b = i / C, c = i % C;
        float cn = fmaxf(g_counts[b], 1.0f);
        s_mean[b][c] = g_sums[b][c] / cn;
    }
    __syncthreads();

    // reset accumulators for the next invocation (state must be zero on entry)
    for (int i = t; i < NB * C; i += 128) ((float*)g_sums)[i] = 0.0f;
    if (t < NB) g_counts[t] = 0.0f;

    {
        int b = t / HID, j = t % HID;
        float acc = b1[j];
        #pragma unroll 8
        for (int c = 0; c < C; c++) acc += s_mean[b][c] * W1[c * HID + j];
        s_h[b][j] = fmaxf(acc, 0.0f);
    }
    __syncthreads();

    {
        int c = t;
        float w2c[HID];
        #pragma unroll
        for (int j = 0; j < HID; j++) w2c[j] = W2[j * C + c];
        float bias = b2[c];
        for (int b = 0; b < NB; b++) {
            float acc = bias;
            #pragma unroll
            for (int j = 0; j < HID; j++) acc += s_h[b][j] * w2c[j];
            g_gate[b][c] = 1.0f / (1.0f + expf(-acc));
        }
    }
}

// ---------------------------------------------------------------------------
// 3) apply gate. SAME chunk mapping as reduce_kernel, but each block walks
//    its chunk DESCENDING: reduce's last-touched rows (chunk tails) are still
//    resident in L2 (~126 MB), so apply's first reads hit. __ldcs / __stcs
//    keep the streaming traffic evict-first so it doesn't flush that set.
// ---------------------------------------------------------------------------
__global__ __launch_bounds__(256) void apply_kernel(
    const float4* __restrict__ x, const int* __restrict__ bidx,
    float4* __restrict__ out, int n, int rows_per_block)
{
    __shared__ float4 s_gate[NB][CV];  // 8 KB
    for (int i = threadIdx.x; i < NB * CV; i += blockDim.x)
        ((float4*)s_gate)[i] = ((const float4*)g_gate)[i];
    __syncthreads();

    int row0 = blockIdx.x * rows_per_block;
    int row1 = row0 + rows_per_block;
    if (row1 > n) row1 = n;
    if (row0 >= row1) return;

    int warp = threadIdx.x >> 5;
    int lane = threadIdx.x & 31;

    // descend from chunk tail; unroll 2 with front-batched loads
    int r = row1 - 1 - warp;
    for (; r - 8 >= row0; r -= 16) {
        int r2 = r - 8;
        int b0 = bidx[r];
        int b1 = bidx[r2];
        float4 v0 = __ldcs(&x[(size_t)r  * CV + lane]);
        float4 v1 = __ldcs(&x[(size_t)r2 * CV + lane]);
        float4 g0 = s_gate[b0][lane];
        float4 g1 = s_gate[b1][lane];
        v0.x *= g0.x; v0.y *= g0.y; v0.z *= g0.z; v0.w *= g0.w;
        v1.x *= g1.x; v1.y *= g1.y; v1.z *= g1.z; v1.w *= g1.w;
        __stcs(&out[(size_t)r  * CV + lane], v0);
        __stcs(&out[(size_t)r2 * CV + lane], v1);
    }
    if (r >= row0) {
        int b = bidx[r];
        float4 v = __ldcs(&x[(size_t)r * CV + lane]);
        float4 g = s_gate[b][lane];
        v.x *= g.x; v.y *= g.y; v.z *= g.z; v.w *= g.w;
        __stcs(&out[(size_t)r * CV + lane], v);
    }
}

// ---------------------------------------------------------------------------
extern "C" void kernel_launch(void* const* d_in, const int* in_sizes, int n_in,
                              void* d_out, int out_size)
{
    const float* x    = (const float*)d_in[0];
    const int*   bidx = (const int*)d_in[1];
    const float* W1   = (const float*)d_in[2];
    const float* b1   = (const float*)d_in[3];
    const float* W2   = (const float*)d_in[4];
    const float* b2   = (const float*)d_in[5];
    float* out = (float*)d_out;

    int n = in_sizes[1];  // number of rows (batch_idx has N entries)
    int rows_per_block = (n + RED_BLOCKS - 1) / RED_BLOCKS;

    reduce_kernel<<<RED_BLOCKS, 256>>>((const float4*)x, bidx, n, rows_per_block);
    mlp_kernel<<<1, 128>>>(W1, b1, W2, b2);
    apply_kernel<<<RED_BLOCKS, 256>>>((const float4*)x, bidx, (float4*)out, n,
                                      rows_per_block);
}